// round 14
// baseline (speedup 1.0000x reference)
#include <cuda_runtime.h>
#include <math.h>
#include <stdint.h>

// ---------------- problem constants ----------------
#define N_TOK 4096
#define HDIM  768
#define FDIM  3072
#define EC    4
#define EU    4
#define CAP   1024

#define BM    128
#define BN    128
#define KC    32              // K per stage (= 2 k-pair chunks of 16)
#define MAXT  36
#define NPOS  (MAXT * BM)
#define KSPLIT 4              // FFN2 split-K factor (wave balance: ~89% util)

#define ABUF  4096            // floats per A stage buffer (128 rows x 32)
#define BBUF  4096            // floats per B stage buffer (32 x 128)

// ---------------- device scratch ----------------
__device__ float g_pmax_c[N_TOK];
__device__ int   g_route_c[N_TOK];
__device__ int   g_route_u[N_TOK];
__device__ int   g_dropped[N_TOK];
__device__ int   g_cnt_c[EC], g_cnt_u[EU];
__device__ int   g_cur_c[EC], g_cur_u[EU];
__device__ int   g_seg_c[EC], g_seg_u[EU];
__device__ int   g_tileE_c[MAXT], g_tileE_u[MAXT];
__device__ int   g_nt_c, g_nt_u;
__device__ int   g_idx_c[NPOS], g_idx_u[NPOS];
__device__ float g_hr[(size_t)N_TOK * HDIM];                 // rna-rounded, frag-permuted
__device__ float g_act[2][(size_t)NPOS * FDIM];              // FFN1 out (frag-permuted)
__device__ float g_w1t[2][(size_t)EC * FDIM * HDIM];         // W1 pair-interleaved frag order
__device__ float g_w2t[2][(size_t)EC * FDIM * HDIM];         // W2 pair-interleaved frag order

// ---------------- helpers ----------------
__device__ __forceinline__ uint32_t smem_u32(const void* p) {
    uint32_t a;
    asm("{ .reg .u64 t; cvta.to.shared.u64 t, %1; cvt.u32.u64 %0, t; }" : "=r"(a) : "l"(p));
    return a;
}
__device__ __forceinline__ float rna_tf32(float v) {
    uint32_t u;
    asm("cvt.rna.tf32.f32 %0, %1;" : "=r"(u) : "f"(v));
    return __uint_as_float(u);
}
__device__ __forceinline__ float gelu_exact(float x) {
    return 0.5f * x * (1.0f + erff(x * 0.7071067811865476f));
}
__device__ __forceinline__ void red_add(float* p, float v) {
    asm volatile("red.global.add.f32 [%0], %1;" :: "l"(p), "f"(v) : "memory");
}
// position of column/k value c within its 16-group (A fragment layout)
__device__ __forceinline__ int kpos(int c) {
    return (c & ~15) + 4 * (c & 3) + ((c & 15) >> 2);
}
#define CPA16(dst, src)  asm volatile("cp.async.cg.shared.global [%0], [%1], 16;" :: "r"(dst), "l"(src))
#define CPCOMMIT()       asm volatile("cp.async.commit_group;" ::: "memory")
#define CPWAIT1()        asm volatile("cp.async.wait_group 1;" ::: "memory")

__device__ __forceinline__ void mma_tf32_16x8x8(float* c,
        float a0, float a1, float a2, float a3, float b0, float b1) {
    asm volatile(
        "mma.sync.aligned.m16n8k8.row.col.f32.tf32.tf32.f32 "
        "{%0,%1,%2,%3}, {%4,%5,%6,%7}, {%8,%9}, {%0,%1,%2,%3};"
        : "+f"(c[0]), "+f"(c[1]), "+f"(c[2]), "+f"(c[3])
        : "r"(__float_as_uint(a0)), "r"(__float_as_uint(a1)),
          "r"(__float_as_uint(a2)), "r"(__float_as_uint(a3)),
          "r"(__float_as_uint(b0)), "r"(__float_as_uint(b1)));
}

// ---------------- 0. reset + zero output (merged) ----------------
__global__ void reset_zero_kernel(float* __restrict__ out) {
    int i = blockIdx.x * blockDim.x + threadIdx.x;
    if (i < EC) { g_cnt_c[i] = 0; g_cur_c[i] = 0; }
    if (i < EU) { g_cnt_u[i] = 0; g_cur_u[i] = 0; }
    int stride = gridDim.x * blockDim.x;
    for (int p = i; p < NPOS; p += stride) {
        g_idx_c[p] = -1;
        g_idx_u[p] = -1;
    }
    for (int p = i; p < N_TOK * HDIM / 4; p += stride)
        ((float4*)out)[p] = make_float4(0.f, 0.f, 0.f, 0.f);
}

// ---------------- 1. router (+ fused rna/frag-permute of hidden states) ----------------
__global__ void router_kernel(const float* __restrict__ h,
                              const float* __restrict__ Wsc, const float* __restrict__ bsc,
                              const float* __restrict__ Wsu, const float* __restrict__ bsu) {
    int gw   = (blockIdx.x * blockDim.x + threadIdx.x) >> 5;
    int lane = threadIdx.x & 31;
    if (gw >= N_TOK) return;
    const float* hr = h + (size_t)gw * HDIM;
    float* hw = g_hr + (size_t)gw * HDIM;
    float a0=0,a1=0,a2=0,a3=0,u0=0,u1=0,u2=0,u3=0;
    for (int k = lane; k < HDIM; k += 32) {
        float x = hr[k];
        hw[kpos(k)] = rna_tf32(x);                      // fused round+permute
        float4 wc = *(const float4*)(Wsc + 4 * k);
        float4 wu = *(const float4*)(Wsu + 4 * k);
        a0 += x*wc.x; a1 += x*wc.y; a2 += x*wc.z; a3 += x*wc.w;
        u0 += x*wu.x; u1 += x*wu.y; u2 += x*wu.z; u3 += x*wu.w;
    }
    #pragma unroll
    for (int o = 16; o > 0; o >>= 1) {
        a0 += __shfl_down_sync(0xffffffffu, a0, o);
        a1 += __shfl_down_sync(0xffffffffu, a1, o);
        a2 += __shfl_down_sync(0xffffffffu, a2, o);
        a3 += __shfl_down_sync(0xffffffffu, a3, o);
        u0 += __shfl_down_sync(0xffffffffu, u0, o);
        u1 += __shfl_down_sync(0xffffffffu, u1, o);
        u2 += __shfl_down_sync(0xffffffffu, u2, o);
        u3 += __shfl_down_sync(0xffffffffu, u3, o);
    }
    if (lane == 0) {
        float lc[4] = {a0 + bsc[0], a1 + bsc[1], a2 + bsc[2], a3 + bsc[3]};
        float lu[4] = {u0 + bsu[0], u1 + bsu[1], u2 + bsu[2], u3 + bsu[3]};
        int rc = 0; float mc = lc[0];
        #pragma unroll
        for (int e = 1; e < EC; e++) if (lc[e] > mc) { mc = lc[e]; rc = e; }
        float s = 0.f;
        #pragma unroll
        for (int e = 0; e < EC; e++) s += expf(lc[e] - mc);
        g_pmax_c[gw]  = 1.0f / s;
        g_route_c[gw] = rc;
        atomicAdd(&g_cnt_c[rc], 1);
        int ru = 0; float mu = lu[0];
        #pragma unroll
        for (int e = 1; e < EU; e++) if (lu[e] > mu) { mu = lu[e]; ru = e; }
        g_route_u[gw] = ru;
    }
}

// ---------------- 2. capacity drop (lexsort rank), 16 threads per token ----------------
// grid 256 x 256: block handles 16 tokens. Chunks are INTERLEAVED (j = sub + 16*jj):
// the 16 sub-lanes hit 16 distinct banks and token-groups broadcast -> conflict-free.
__global__ void __launch_bounds__(256) drop_kernel() {
    __shared__ float sp[N_TOK];
    __shared__ unsigned char sr[N_TOK];
    int tid = threadIdx.x;
    for (int j = tid; j < N_TOK; j += blockDim.x) {
        sp[j] = g_pmax_c[j];
        sr[j] = (unsigned char)g_route_c[j];
    }
    __syncthreads();
    int tloc = tid >> 4;                       // token within block (0..15)
    int sub  = tid & 15;                       // interleave phase (0..15)
    int i = blockIdx.x * 16 + tloc;            // global token
    float pi = sp[i];
    unsigned char re = sr[i];
    int cnt = 0;
    #pragma unroll 8
    for (int jj = 0; jj < N_TOK / 16; jj++) {
        int j = sub + 16 * jj;                 // interleaved: conflict-free LDS
        float pj = sp[j];
        bool before = (pj > pi) || (pj == pi && j < i);
        cnt += (sr[j] == re) && before;
    }
    #pragma unroll
    for (int o = 8; o > 0; o >>= 1)
        cnt += __shfl_down_sync(0xffffffffu, cnt, o, 16);
    if (sub == 0) {
        int drp = (cnt >= CAP) ? 1 : 0;
        g_dropped[i] = drp;
        if (drp) atomicAdd(&g_cnt_u[g_route_u[i]], 1);
    }
}

// ---------------- 3. tile tables ----------------
__global__ void build_tiles_kernel() {
    if (threadIdx.x == 0 && blockIdx.x == 0) {
        int base = 0, t = 0;
        for (int e = 0; e < EC; e++) {
            g_seg_c[e] = base;
            int tiles = (g_cnt_c[e] + BM - 1) / BM;
            for (int i = 0; i < tiles; i++) g_tileE_c[t++] = e;
            base += tiles * BM;
        }
        g_nt_c = t;
        base = 0; t = 0;
        for (int e = 0; e < EU; e++) {
            g_seg_u[e] = base;
            int tiles = (g_cnt_u[e] + BM - 1) / BM;
            for (int i = 0; i < tiles; i++) g_tileE_u[t++] = e;
            base += tiles * BM;
        }
        g_nt_u = t;
    }
}

// ---------------- 4. scatter ----------------
__global__ void scatter_kernel() {
    int i = blockIdx.x * blockDim.x + threadIdx.x;
    if (i >= N_TOK) return;
    int e = g_route_c[i];
    int p = g_seg_c[e] + atomicAdd(&g_cur_c[e], 1);
    g_idx_c[p] = i;
    if (g_dropped[i]) {
        int eu = g_route_u[i];
        int q = g_seg_u[eu] + atomicAdd(&g_cur_u[eu], 1);
        g_idx_u[q] = i;
    }
}

// ---------------- 5. permute weights into pair-interleaved B-fragment order ----------------
__global__ void __launch_bounds__(256) permute_all_kernel(
        const float* __restrict__ W1c, const float* __restrict__ W1u,
        const float* __restrict__ W2c, const float* __restrict__ W2u) {
    __shared__ float t[32][136];
    const int TPW = 576;                            // tiles per (wg, expert)
    int bid = blockIdx.x;
    int which = bid / TPW;                          // 0..15
    int tile  = bid % TPW;
    int wg = which >> 2, e = which & 3;
    int Kd = (wg < 2) ? HDIM : FDIM;
    int Nd = (wg < 2) ? FDIM : HDIM;
    const float* srcs[4] = {W1c, W1u, W2c, W2u};
    float* dsts[4] = {g_w1t[0], g_w1t[1], g_w2t[0], g_w2t[1]};
    const float* s = srcs[wg] + (size_t)e * Kd * Nd;
    float* d = dsts[wg] + (size_t)e * Kd * Nd;
    int tilesN = Nd / 128;
    int k0 = (tile / tilesN) * 32, n0 = (tile % tilesN) * 128;

    int tid = threadIdx.x;
    int lr = tid >> 5, lc = (tid & 31) * 4;
    #pragma unroll
    for (int i = 0; i < 4; i++) {
        int r = lr + 8 * i;
        float4 v = *(const float4*)(s + (size_t)(k0 + r) * Nd + n0 + lc);
        *(float4*)&t[r][lc] = v;
    }
    __syncthreads();
    int lane = tid & 31;
    #pragma unroll
    for (int it = 0; it < 4; it++) {
        int chunk = (tid >> 5) + 8 * it;
        int kp = chunk & 1, nb = chunk >> 1;
        int kloc = kp * 16 + (lane & 3);
        int nloc = nb * 8 + (lane >> 2);
        float4 v;
        v.x = rna_tf32(t[kloc][nloc]);
        v.y = rna_tf32(t[kloc + 4][nloc]);
        v.z = rna_tf32(t[kloc + 8][nloc]);
        v.w = rna_tf32(t[kloc + 12][nloc]);
        size_t base = ((size_t)(n0 / 8 + nb) * (Kd / 16) + (k0 / 16 + kp)) * 128 + lane * 4;
        *(float4*)(d + base) = v;
    }
}

// ============================================================================
// GEMM core: triple-buffered, ONE barrier/stage, float4 A fragments (XOR swizzle)
// ============================================================================

// ---------------- 6. FFN1 (fused common+unique) ----------------
__global__ void __launch_bounds__(256) ffn1_mma(const float* __restrict__ b1c,
                                                const float* __restrict__ b1u) {
    extern __shared__ float sm[];
    int uniq = blockIdx.y >= MAXT;
    int mt = blockIdx.y - (uniq ? MAXT : 0);
    int nt = uniq ? g_nt_u : g_nt_c;
    if (mt >= nt) return;
    const int* idx = uniq ? g_idx_u : g_idx_c;
    int e  = (uniq ? g_tileE_u : g_tileE_c)[mt];
    int n0 = blockIdx.x * BN;
    const float* Bw = g_w1t[uniq] + (size_t)e * HDIM * FDIM;
    const float* bb = (uniq ? b1u : b1c) + e * FDIM;
    float* act = g_act[uniq];

    uint32_t A0a = smem_u32(sm);
    uint32_t B0a = smem_u32(sm + 3 * ABUF);

    int tid = threadIdx.x;
    int lr = tid >> 1, hh = tid & 1;
    int tokr = idx[mt * BM + lr];
    const float* aptr = g_hr + (size_t)(tokr < 0 ? 0 : tokr) * HDIM + hh * 16;
    uint32_t adst = (uint32_t)(lr * 32 + ((hh ^ (lr & 1)) * 16)) * 4u;

    const int NST = HDIM / KC;   // 24
    #define FFN1_ISSUE(s, bw) do {                                                 \
        uint32_t Aa = A0a + (uint32_t)(bw) * (ABUF * 4u);                          \
        uint32_t Ba = B0a + (uint32_t)(bw) * (BBUF * 4u);                          \
        const float* ap = aptr + (s) * KC;                                         \
        _Pragma("unroll")                                                          \
        for (int i = 0; i < 4; i++) CPA16(Aa + adst + i * 16u, ap + i * 4);        \
        _Pragma("unroll")                                                          \
        for (int i = 0; i < 4; i++) {                                              \
            int ft = i * 256 + tid;                                                \
            int c128 = ft >> 5, slot = ft & 31;                                    \
            int nb_l = c128 >> 1, kp_l = c128 & 1;                                 \
            const float* bp = Bw + ((size_t)(n0 / 8 + nb_l) * (HDIM / 16)          \
                                    + (2 * (s) + kp_l)) * 128 + slot * 4;          \
            CPA16(Ba + (uint32_t)(c128 * 128 + slot * 4) * 4u, bp);                \
        }                                                                          \
    } while (0)

    FFN1_ISSUE(0, 0); CPCOMMIT();
    FFN1_ISSUE(1, 1); CPCOMMIT();

    int wid = tid >> 5, lane = tid & 31;
    int wm = wid & 3, wn = wid >> 2;
    int r4 = lane >> 2, kl = lane & 3;
    int rpar4 = (r4 & 1) * 4;

    float acc[2][8][4];
    #pragma unroll
    for (int m = 0; m < 2; m++)
        #pragma unroll
        for (int j = 0; j < 8; j++)
            #pragma unroll
            for (int q = 0; q < 4; q++) acc[m][j][q] = 0.f;

    int bc = 0;
    for (int s = 0; s < NST; s++) {
        CPWAIT1();
        __syncthreads();
        int bw = bc + 2; if (bw >= 3) bw -= 3;
        if (s + 2 < NST) FFN1_ISSUE(s + 2, bw);
        CPCOMMIT();
        const float* As = sm + bc * ABUF;
        const float* Bs = sm + 3 * ABUF + bc * BBUF;
        #pragma unroll
        for (int kp = 0; kp < 2; kp++) {
            float4 va[2][2];
            int sc = ((kp * 4) ^ rpar4) + kl;
            #pragma unroll
            for (int m = 0; m < 2; m++) {
                int row0 = wm * 32 + m * 16 + r4;
                va[m][0] = *(const float4*)(As + row0 * 32 + sc * 4);
                va[m][1] = *(const float4*)(As + (row0 + 8) * 32 + sc * 4);
            }
            #pragma unroll
            for (int j = 0; j < 8; j++) {
                float4 b4 = *(const float4*)&Bs[(((wn * 8 + j) * 2 + kp) * 128) + lane * 4];
                #pragma unroll
                for (int m = 0; m < 2; m++) {
                    mma_tf32_16x8x8(acc[m][j], va[m][0].x, va[m][1].x,
                                    va[m][0].y, va[m][1].y, b4.x, b4.y);
                    mma_tf32_16x8x8(acc[m][j], va[m][0].z, va[m][1].z,
                                    va[m][0].w, va[m][1].w, b4.z, b4.w);
                }
            }
        }
        bc = (bc == 2) ? 0 : bc + 1;
    }
    #undef FFN1_ISSUE

    // epilogue: bias + gelu, scattered into frag-permuted positions of act
    #pragma unroll
    for (int m = 0; m < 2; m++) {
        int r0 = mt * BM + wm * 32 + m * 16 + r4;
        #pragma unroll
        for (int j = 0; j < 8; j++) {
            int gb = n0 + wn * 64 + j * 8;
            int c0 = gb + 2 * kl, c1 = c0 + 1;
            int p0 = kpos(c0), p1 = kpos(c1);
            float b0 = bb[c0], b1 = bb[c1];
            size_t ra = (size_t)r0 * FDIM;
            size_t rb = (size_t)(r0 + 8) * FDIM;
            act[ra + p0] = rna_tf32(gelu_exact(acc[m][j][0] + b0));
            act[ra + p1] = rna_tf32(gelu_exact(acc[m][j][1] + b1));
            act[rb + p0] = rna_tf32(gelu_exact(acc[m][j][2] + b0));
            act[rb + p1] = rna_tf32(gelu_exact(acc[m][j][3] + b1));
        }
    }
}

// ---------------- 7. FFN2 (fused common+unique, split-K x4): out += partial via RED ----------------
__global__ void __launch_bounds__(256) ffn2_mma(const float* __restrict__ b2c,
                                                const float* __restrict__ b2u,
                                                float* __restrict__ out) {
    extern __shared__ float sm[];
    int uniq = blockIdx.y >= MAXT;
    int mt = blockIdx.y - (uniq ? MAXT : 0);
    int nt = uniq ? g_nt_u : g_nt_c;
    if (mt >= nt) return;
    const int* idx = uniq ? g_idx_u : g_idx_c;
    int e  = (uniq ? g_tileE_u : g_tileE_c)[mt];
    int n0 = blockIdx.x * BN;
    const int NSTH = FDIM / KC / KSPLIT;          // 24 stages per split
    int koff = blockIdx.z * NSTH;
    const float* Bw = g_w2t[uniq] + (size_t)e * FDIM * HDIM;
    const float* bb = (uniq ? b2u : b2c) + e * HDIM;
    const float* act = g_act[uniq];

    uint32_t A0a = smem_u32(sm);
    uint32_t B0a = smem_u32(sm + 3 * ABUF);

    int tid = threadIdx.x;
    int lr = tid >> 1, hh = tid & 1;
    const float* aptr = act + (size_t)(mt * BM + lr) * FDIM + hh * 16 + koff * KC;
    uint32_t adst = (uint32_t)(lr * 32 + ((hh ^ (lr & 1)) * 16)) * 4u;

    #define FFN2_ISSUE(s, bw) do {                                                 \
        uint32_t Aa = A0a + (uint32_t)(bw) * (ABUF * 4u);                          \
        uint32_t Ba = B0a + (uint32_t)(bw) * (BBUF * 4u);                          \
        const float* ap = aptr + (s) * KC;                                         \
        _Pragma("unroll")                                                          \
        for (int i = 0; i < 4; i++) CPA16(Aa + adst + i * 16u, ap + i * 4);        \
        _Pragma("unroll")                                                          \
        for (int i = 0; i < 4; i++) {                                              \
            int ft = i * 256 + tid;                                                \
            int c128 = ft >> 5, slot = ft & 31;                                    \
            int nb_l = c128 >> 1, kp_l = c128 & 1;                                 \
            const float* bp = Bw + ((size_t)(n0 / 8 + nb_l) * (FDIM / 16)          \
                                    + (2 * ((s) + koff) + kp_l)) * 128 + slot * 4; \
            CPA16(Ba + (uint32_t)(c128 * 128 + slot * 4) * 4u, bp);                \
        }                                                                          \
    } while (0)

    FFN2_ISSUE(0, 0); CPCOMMIT();
    FFN2_ISSUE(1, 1); CPCOMMIT();

    int wid = tid >> 5, lane = tid & 31;
    int wm = wid & 3, wn = wid >> 2;
    int r4 = lane >> 2, kl = lane & 3;
    int rpar4 = (r4 & 1) * 4;

    float acc[2][8][4];
    #pragma unroll
    for (int m = 0; m < 2; m++)
        #pragma unroll
        for (int j = 0; j < 8; j++)
            #pragma unroll
            for (int q = 0; q < 4; q++) acc[m][j][q] = 0.f;

    int bc = 0;
    for (int s = 0; s < NSTH; s++) {
        CPWAIT1();
        __syncthreads();
        int bw = bc + 2; if (bw >= 3) bw -= 3;
        if (s + 2 < NSTH) FFN2_ISSUE(s + 2, bw);
        CPCOMMIT();
        const float* As = sm + bc * ABUF;
        const float* Bs = sm + 3 * ABUF + bc * BBUF;
        #pragma unroll
        for (int kp = 0; kp < 2; kp++) {
            float4 va[2][2];
            int sc = ((kp * 4) ^ rpar4) + kl;
            #pragma unroll
            for (int m = 0; m < 2; m++) {
                int row0 = wm * 32 + m * 16 + r4;
                va[m][0] = *(const float4*)(As + row0 * 32 + sc * 4);
                va[m][1] = *(const float4*)(As + (row0 + 8) * 32 + sc * 4);
            }
            #pragma unroll
            for (int j = 0; j < 8; j++) {
                float4 b4 = *(const float4*)&Bs[(((wn * 8 + j) * 2 + kp) * 128) + lane * 4];
                #pragma unroll
                for (int m = 0; m < 2; m++) {
                    mma_tf32_16x8x8(acc[m][j], va[m][0].x, va[m][1].x,
                                    va[m][0].y, va[m][1].y, b4.x, b4.y);
                    mma_tf32_16x8x8(acc[m][j], va[m][0].z, va[m][1].z,
                                    va[m][0].w, va[m][1].w, b4.z, b4.w);
                }
            }
        }
        bc = (bc == 2) ? 0 : bc + 1;
    }
    #undef FFN2_ISSUE

    // epilogue: RED-accumulate partial (+bias only from split 0) into pre-zeroed out
    int addb = (koff == 0);
    #pragma unroll
    for (int m = 0; m < 2; m++) {
        int rbase = mt * BM + wm * 32 + m * 16 + r4;
        #pragma unroll
        for (int rr = 0; rr < 2; rr++) {
            int tok = idx[rbase + rr * 8];
            if (tok < 0) continue;
            float* orow = out + (size_t)tok * HDIM;
            #pragma unroll
            for (int j = 0; j < 8; j++) {
                int col = n0 + wn * 64 + j * 8 + 2 * kl;
                float bv0 = addb ? bb[col]     : 0.f;
                float bv1 = addb ? bb[col + 1] : 0.f;
                red_add(orow + col,     acc[m][j][rr * 2 + 0] + bv0);
                red_add(orow + col + 1, acc[m][j][rr * 2 + 1] + bv1);
            }
        }
    }
}

// ---------------- launch ----------------
extern "C" void kernel_launch(void* const* d_in, const int* in_sizes, int n_in,
                              void* d_out, int out_size) {
    const float* h   = (const float*)d_in[0];
    const float* Wsc = (const float*)d_in[1];
    const float* bsc = (const float*)d_in[2];
    const float* W1c = (const float*)d_in[3];
    const float* b1c = (const float*)d_in[4];
    const float* W2c = (const float*)d_in[5];
    const float* b2c = (const float*)d_in[6];
    const float* Wsu = (const float*)d_in[7];
    const float* bsu = (const float*)d_in[8];
    const float* W1u = (const float*)d_in[9];
    const float* b1u = (const float*)d_in[10];
    const float* W2u = (const float*)d_in[11];
    const float* b2u = (const float*)d_in[12];
    float* out = (float*)d_out;

    const int SMEM = 3 * (ABUF + BBUF) * 4;   // 98304 B
    cudaFuncSetAttribute(ffn1_mma, cudaFuncAttributeMaxDynamicSharedMemorySize, SMEM);
    cudaFuncSetAttribute(ffn2_mma, cudaFuncAttributeMaxDynamicSharedMemorySize, SMEM);

    // weight permutes (coalesced 32x128-region kernel)
    permute_all_kernel<<<16 * 576, 256>>>(W1c, W1u, W2c, W2u);

    // routing (router also produces rounded/permuted g_hr)
    reset_zero_kernel<<<592, 256>>>(out);
    router_kernel<<<512, 256>>>(h, Wsc, bsc, Wsu, bsu);
    drop_kernel<<<256, 256>>>();
    build_tiles_kernel<<<1, 32>>>();
    scatter_kernel<<<16, 256>>>();

    // FFN1 fused (common + unique)
    ffn1_mma<<<dim3(FDIM / BN, 2 * MAXT), 256, SMEM>>>(b1c, b1u);
    // FFN2 fused (common + unique) with split-K x4, RED epilogue into zeroed out
    ffn2_mma<<<dim3(HDIM / BN, 2 * MAXT, KSPLIT), 256, SMEM>>>(b2c, b2u, out);
}

// round 16
// speedup vs baseline: 1.0411x; 1.0411x over previous
#include <cuda_runtime.h>
#include <math.h>
#include <stdint.h>

// ---------------- problem constants ----------------
#define N_TOK 4096
#define HDIM  768
#define FDIM  3072
#define EC    4
#define EU    4
#define CAP   1024

#define BM    128
#define BN    128
#define KC    32              // K per stage (= 2 k-pair chunks of 16)
#define MAXT  36
#define NPOS  (MAXT * BM)
#define KSPLIT 2              // FFN2 split-K factor (R10-proven)

#define ABUF  4096            // floats per A stage buffer (128 rows x 32)
#define BBUF  4096            // floats per B stage buffer (32 x 128)

#define PERM_BLOCKS (16 * 576)   // weight-permute blocks
#define RESET_BLOCKS 592         // extra blocks doing reset/zero work

// ---------------- device scratch ----------------
__device__ float g_pmax_c[N_TOK];
__device__ int   g_route_c[N_TOK];
__device__ int   g_route_u[N_TOK];
__device__ int   g_dropped[N_TOK];
__device__ int   g_cnt_c[EC], g_cnt_u[EU];
__device__ int   g_tileE_c[MAXT], g_tileE_u[MAXT];
__device__ int   g_nt_c, g_nt_u;
__device__ int   g_idx_c[NPOS], g_idx_u[NPOS];
__device__ float g_hr[(size_t)N_TOK * HDIM];                 // rna-rounded, frag-permuted
__device__ float g_act[2][(size_t)NPOS * FDIM];              // FFN1 out (frag-permuted)
__device__ float g_w1t[2][(size_t)EC * FDIM * HDIM];         // W1 pair-interleaved frag order
__device__ float g_w2t[2][(size_t)EC * FDIM * HDIM];         // W2 pair-interleaved frag order

// ---------------- helpers ----------------
__device__ __forceinline__ uint32_t smem_u32(const void* p) {
    uint32_t a;
    asm("{ .reg .u64 t; cvta.to.shared.u64 t, %1; cvt.u32.u64 %0, t; }" : "=r"(a) : "l"(p));
    return a;
}
__device__ __forceinline__ float rna_tf32(float v) {
    uint32_t u;
    asm("cvt.rna.tf32.f32 %0, %1;" : "=r"(u) : "f"(v));
    return __uint_as_float(u);
}
__device__ __forceinline__ float gelu_exact(float x) {
    return 0.5f * x * (1.0f + erff(x * 0.7071067811865476f));
}
__device__ __forceinline__ void red_add(float* p, float v) {
    asm volatile("red.global.add.f32 [%0], %1;" :: "l"(p), "f"(v) : "memory");
}
// position of column/k value c within its 16-group (A fragment layout)
__device__ __forceinline__ int kpos(int c) {
    return (c & ~15) + 4 * (c & 3) + ((c & 15) >> 2);
}
#define CPA16(dst, src)  asm volatile("cp.async.cg.shared.global [%0], [%1], 16;" :: "r"(dst), "l"(src))
#define CPCOMMIT()       asm volatile("cp.async.commit_group;" ::: "memory")
#define CPWAIT1()        asm volatile("cp.async.wait_group 1;" ::: "memory")

__device__ __forceinline__ void mma_tf32_16x8x8(float* c,
        float a0, float a1, float a2, float a3, float b0, float b1) {
    asm volatile(
        "mma.sync.aligned.m16n8k8.row.col.f32.tf32.tf32.f32 "
        "{%0,%1,%2,%3}, {%4,%5,%6,%7}, {%8,%9}, {%0,%1,%2,%3};"
        : "+f"(c[0]), "+f"(c[1]), "+f"(c[2]), "+f"(c[3])
        : "r"(__float_as_uint(a0)), "r"(__float_as_uint(a1)),
          "r"(__float_as_uint(a2)), "r"(__float_as_uint(a3)),
          "r"(__float_as_uint(b0)), "r"(__float_as_uint(b1)));
}

// ---------------- 1. permute weights (+ fold in reset/zero as extra blocks) ----------------
// blocks [0, PERM_BLOCKS): permute one (wg, expert) 32(k) x 128(n) region.
// blocks [PERM_BLOCKS, PERM_BLOCKS+RESET_BLOCKS): reset counters / idx / zero out.
__global__ void __launch_bounds__(256) permute_reset_kernel(
        const float* __restrict__ W1c, const float* __restrict__ W1u,
        const float* __restrict__ W2c, const float* __restrict__ W2u,
        float* __restrict__ out) {
    __shared__ float t[32][136];
    int bid = blockIdx.x;
    int tid = threadIdx.x;
    if (bid >= PERM_BLOCKS) {
        // ---- reset/zero work ----
        int rb = bid - PERM_BLOCKS;
        int i = rb * 256 + tid;
        if (i < EC) g_cnt_c[i] = 0;
        if (i < EU) g_cnt_u[i] = 0;
        int stride = RESET_BLOCKS * 256;
        for (int p = i; p < NPOS; p += stride) {
            g_idx_c[p] = -1;
            g_idx_u[p] = -1;
        }
        for (int p = i; p < N_TOK * HDIM / 4; p += stride)
            ((float4*)out)[p] = make_float4(0.f, 0.f, 0.f, 0.f);
        return;
    }
    const int TPW = 576;                            // tiles per (wg, expert)
    int which = bid / TPW;                          // 0..15
    int tile  = bid % TPW;
    int wg = which >> 2, e = which & 3;
    int Kd = (wg < 2) ? HDIM : FDIM;
    int Nd = (wg < 2) ? FDIM : HDIM;
    const float* srcs[4] = {W1c, W1u, W2c, W2u};
    float* dsts[4] = {g_w1t[0], g_w1t[1], g_w2t[0], g_w2t[1]};
    const float* s = srcs[wg] + (size_t)e * Kd * Nd;
    float* d = dsts[wg] + (size_t)e * Kd * Nd;
    int tilesN = Nd / 128;
    int k0 = (tile / tilesN) * 32, n0 = (tile % tilesN) * 128;

    int lr = tid >> 5, lc = (tid & 31) * 4;
    #pragma unroll
    for (int i = 0; i < 4; i++) {
        int r = lr + 8 * i;
        float4 v = *(const float4*)(s + (size_t)(k0 + r) * Nd + n0 + lc);
        *(float4*)&t[r][lc] = v;
    }
    __syncthreads();
    int lane = tid & 31;
    #pragma unroll
    for (int it = 0; it < 4; it++) {
        int chunk = (tid >> 5) + 8 * it;
        int kp = chunk & 1, nb = chunk >> 1;
        int kloc = kp * 16 + (lane & 3);
        int nloc = nb * 8 + (lane >> 2);
        float4 v;
        v.x = rna_tf32(t[kloc][nloc]);
        v.y = rna_tf32(t[kloc + 4][nloc]);
        v.z = rna_tf32(t[kloc + 8][nloc]);
        v.w = rna_tf32(t[kloc + 12][nloc]);
        size_t base = ((size_t)(n0 / 8 + nb) * (Kd / 16) + (k0 / 16 + kp)) * 128 + lane * 4;
        *(float4*)(d + base) = v;
    }
}

// ---------------- 2. router (+ fused rna/frag-permute of hidden states) ----------------
__global__ void router_kernel(const float* __restrict__ h,
                              const float* __restrict__ Wsc, const float* __restrict__ bsc,
                              const float* __restrict__ Wsu, const float* __restrict__ bsu) {
    int gw   = (blockIdx.x * blockDim.x + threadIdx.x) >> 5;
    int lane = threadIdx.x & 31;
    if (gw >= N_TOK) return;
    const float* hr = h + (size_t)gw * HDIM;
    float* hw = g_hr + (size_t)gw * HDIM;
    float a0=0,a1=0,a2=0,a3=0,u0=0,u1=0,u2=0,u3=0;
    for (int k = lane; k < HDIM; k += 32) {
        float x = hr[k];
        hw[kpos(k)] = rna_tf32(x);                      // fused round+permute
        float4 wc = *(const float4*)(Wsc + 4 * k);
        float4 wu = *(const float4*)(Wsu + 4 * k);
        a0 += x*wc.x; a1 += x*wc.y; a2 += x*wc.z; a3 += x*wc.w;
        u0 += x*wu.x; u1 += x*wu.y; u2 += x*wu.z; u3 += x*wu.w;
    }
    #pragma unroll
    for (int o = 16; o > 0; o >>= 1) {
        a0 += __shfl_down_sync(0xffffffffu, a0, o);
        a1 += __shfl_down_sync(0xffffffffu, a1, o);
        a2 += __shfl_down_sync(0xffffffffu, a2, o);
        a3 += __shfl_down_sync(0xffffffffu, a3, o);
        u0 += __shfl_down_sync(0xffffffffu, u0, o);
        u1 += __shfl_down_sync(0xffffffffu, u1, o);
        u2 += __shfl_down_sync(0xffffffffu, u2, o);
        u3 += __shfl_down_sync(0xffffffffu, u3, o);
    }
    if (lane == 0) {
        float lc[4] = {a0 + bsc[0], a1 + bsc[1], a2 + bsc[2], a3 + bsc[3]};
        float lu[4] = {u0 + bsu[0], u1 + bsu[1], u2 + bsu[2], u3 + bsu[3]};
        int rc = 0; float mc = lc[0];
        #pragma unroll
        for (int e = 1; e < EC; e++) if (lc[e] > mc) { mc = lc[e]; rc = e; }
        float s = 0.f;
        #pragma unroll
        for (int e = 0; e < EC; e++) s += expf(lc[e] - mc);
        g_pmax_c[gw]  = 1.0f / s;
        g_route_c[gw] = rc;
        atomicAdd(&g_cnt_c[rc], 1);
        int ru = 0; float mu = lu[0];
        #pragma unroll
        for (int e = 1; e < EU; e++) if (lu[e] > mu) { mu = lu[e]; ru = e; }
        g_route_u[gw] = ru;
    }
}

// ---------------- 3. capacity drop (lexsort rank), 16 threads per token ----------------
__global__ void __launch_bounds__(256) drop_kernel() {
    __shared__ float sp[N_TOK];
    __shared__ unsigned char sr[N_TOK];
    int tid = threadIdx.x;
    for (int j = tid; j < N_TOK; j += blockDim.x) {
        sp[j] = g_pmax_c[j];
        sr[j] = (unsigned char)g_route_c[j];
    }
    __syncthreads();
    int tloc = tid >> 4;                       // token within block (0..15)
    int sub  = tid & 15;                       // interleave phase (0..15)
    int i = blockIdx.x * 16 + tloc;            // global token
    float pi = sp[i];
    unsigned char re = sr[i];
    int cnt = 0;
    #pragma unroll 8
    for (int jj = 0; jj < N_TOK / 16; jj++) {
        int j = sub + 16 * jj;                 // interleaved: conflict-free LDS
        float pj = sp[j];
        bool before = (pj > pi) || (pj == pi && j < i);
        cnt += (sr[j] == re) && before;
    }
    #pragma unroll
    for (int o = 8; o > 0; o >>= 1)
        cnt += __shfl_down_sync(0xffffffffu, cnt, o, 16);
    if (sub == 0) {
        int drp = (cnt >= CAP) ? 1 : 0;
        g_dropped[i] = drp;
        if (drp) atomicAdd(&g_cnt_u[g_route_u[i]], 1);
    }
}

// ---------------- 4. build tile tables + scatter (merged, single block) ----------------
__global__ void __launch_bounds__(256) build_scatter_kernel() {
    __shared__ int seg_c[EC], seg_u[EU];
    __shared__ int cur_c[EC], cur_u[EU];
    int tid = threadIdx.x;
    if (tid == 0) {
        int base = 0, t = 0;
        for (int e = 0; e < EC; e++) {
            seg_c[e] = base;
            int tiles = (g_cnt_c[e] + BM - 1) / BM;
            for (int i = 0; i < tiles; i++) g_tileE_c[t++] = e;
            base += tiles * BM;
        }
        g_nt_c = t;
        base = 0; t = 0;
        for (int e = 0; e < EU; e++) {
            seg_u[e] = base;
            int tiles = (g_cnt_u[e] + BM - 1) / BM;
            for (int i = 0; i < tiles; i++) g_tileE_u[t++] = e;
            base += tiles * BM;
        }
        g_nt_u = t;
    }
    if (tid < EC) cur_c[tid] = 0;
    if (tid < EU) cur_u[tid] = 0;
    __syncthreads();
    for (int i = tid; i < N_TOK; i += 256) {
        int e = g_route_c[i];
        int p = seg_c[e] + atomicAdd(&cur_c[e], 1);
        g_idx_c[p] = i;
        if (g_dropped[i]) {
            int eu = g_route_u[i];
            int q = seg_u[eu] + atomicAdd(&cur_u[eu], 1);
            g_idx_u[q] = i;
        }
    }
}

// ============================================================================
// GEMM core: triple-buffered, ONE barrier/stage, float4 A fragments (XOR swizzle)
// ============================================================================

// ---------------- 5. FFN1 (fused common+unique) ----------------
__global__ void __launch_bounds__(256) ffn1_mma(const float* __restrict__ b1c,
                                                const float* __restrict__ b1u) {
    extern __shared__ float sm[];
    int uniq = blockIdx.y >= MAXT;
    int mt = blockIdx.y - (uniq ? MAXT : 0);
    int nt = uniq ? g_nt_u : g_nt_c;
    if (mt >= nt) return;
    const int* idx = uniq ? g_idx_u : g_idx_c;
    int e  = (uniq ? g_tileE_u : g_tileE_c)[mt];
    int n0 = blockIdx.x * BN;
    const float* Bw = g_w1t[uniq] + (size_t)e * HDIM * FDIM;
    const float* bb = (uniq ? b1u : b1c) + e * FDIM;
    float* act = g_act[uniq];

    uint32_t A0a = smem_u32(sm);
    uint32_t B0a = smem_u32(sm + 3 * ABUF);

    int tid = threadIdx.x;
    int lr = tid >> 1, hh = tid & 1;
    int tokr = idx[mt * BM + lr];
    const float* aptr = g_hr + (size_t)(tokr < 0 ? 0 : tokr) * HDIM + hh * 16;
    uint32_t adst = (uint32_t)(lr * 32 + ((hh ^ (lr & 1)) * 16)) * 4u;

    const int NST = HDIM / KC;   // 24
    #define FFN1_ISSUE(s, bw) do {                                                 \
        uint32_t Aa = A0a + (uint32_t)(bw) * (ABUF * 4u);                          \
        uint32_t Ba = B0a + (uint32_t)(bw) * (BBUF * 4u);                          \
        const float* ap = aptr + (s) * KC;                                         \
        _Pragma("unroll")                                                          \
        for (int i = 0; i < 4; i++) CPA16(Aa + adst + i * 16u, ap + i * 4);        \
        _Pragma("unroll")                                                          \
        for (int i = 0; i < 4; i++) {                                              \
            int ft = i * 256 + tid;                                                \
            int c128 = ft >> 5, slot = ft & 31;                                    \
            int nb_l = c128 >> 1, kp_l = c128 & 1;                                 \
            const float* bp = Bw + ((size_t)(n0 / 8 + nb_l) * (HDIM / 16)          \
                                    + (2 * (s) + kp_l)) * 128 + slot * 4;          \
            CPA16(Ba + (uint32_t)(c128 * 128 + slot * 4) * 4u, bp);                \
        }                                                                          \
    } while (0)

    FFN1_ISSUE(0, 0); CPCOMMIT();
    FFN1_ISSUE(1, 1); CPCOMMIT();

    int wid = tid >> 5, lane = tid & 31;
    int wm = wid & 3, wn = wid >> 2;
    int r4 = lane >> 2, kl = lane & 3;
    int rpar4 = (r4 & 1) * 4;

    float acc[2][8][4];
    #pragma unroll
    for (int m = 0; m < 2; m++)
        #pragma unroll
        for (int j = 0; j < 8; j++)
            #pragma unroll
            for (int q = 0; q < 4; q++) acc[m][j][q] = 0.f;

    int bc = 0;
    for (int s = 0; s < NST; s++) {
        CPWAIT1();
        __syncthreads();
        int bw = bc + 2; if (bw >= 3) bw -= 3;
        if (s + 2 < NST) FFN1_ISSUE(s + 2, bw);
        CPCOMMIT();
        const float* As = sm + bc * ABUF;
        const float* Bs = sm + 3 * ABUF + bc * BBUF;
        #pragma unroll
        for (int kp = 0; kp < 2; kp++) {
            float4 va[2][2];
            int sc = ((kp * 4) ^ rpar4) + kl;
            #pragma unroll
            for (int m = 0; m < 2; m++) {
                int row0 = wm * 32 + m * 16 + r4;
                va[m][0] = *(const float4*)(As + row0 * 32 + sc * 4);
                va[m][1] = *(const float4*)(As + (row0 + 8) * 32 + sc * 4);
            }
            #pragma unroll
            for (int j = 0; j < 8; j++) {
                float4 b4 = *(const float4*)&Bs[(((wn * 8 + j) * 2 + kp) * 128) + lane * 4];
                #pragma unroll
                for (int m = 0; m < 2; m++) {
                    mma_tf32_16x8x8(acc[m][j], va[m][0].x, va[m][1].x,
                                    va[m][0].y, va[m][1].y, b4.x, b4.y);
                    mma_tf32_16x8x8(acc[m][j], va[m][0].z, va[m][1].z,
                                    va[m][0].w, va[m][1].w, b4.z, b4.w);
                }
            }
        }
        bc = (bc == 2) ? 0 : bc + 1;
    }
    #undef FFN1_ISSUE

    // epilogue: bias + gelu, scattered into frag-permuted positions of act
    #pragma unroll
    for (int m = 0; m < 2; m++) {
        int r0 = mt * BM + wm * 32 + m * 16 + r4;
        #pragma unroll
        for (int j = 0; j < 8; j++) {
            int gb = n0 + wn * 64 + j * 8;
            int c0 = gb + 2 * kl, c1 = c0 + 1;
            int p0 = kpos(c0), p1 = kpos(c1);
            float b0 = bb[c0], b1 = bb[c1];
            size_t ra = (size_t)r0 * FDIM;
            size_t rb = (size_t)(r0 + 8) * FDIM;
            act[ra + p0] = rna_tf32(gelu_exact(acc[m][j][0] + b0));
            act[ra + p1] = rna_tf32(gelu_exact(acc[m][j][1] + b1));
            act[rb + p0] = rna_tf32(gelu_exact(acc[m][j][2] + b0));
            act[rb + p1] = rna_tf32(gelu_exact(acc[m][j][3] + b1));
        }
    }
}

// ---------------- 6. FFN2 (fused common+unique, split-K x2): out += partial via RED ----------------
__global__ void __launch_bounds__(256) ffn2_mma(const float* __restrict__ b2c,
                                                const float* __restrict__ b2u,
                                                float* __restrict__ out) {
    extern __shared__ float sm[];
    int uniq = blockIdx.y >= MAXT;
    int mt = blockIdx.y - (uniq ? MAXT : 0);
    int nt = uniq ? g_nt_u : g_nt_c;
    if (mt >= nt) return;
    const int* idx = uniq ? g_idx_u : g_idx_c;
    int e  = (uniq ? g_tileE_u : g_tileE_c)[mt];
    int n0 = blockIdx.x * BN;
    const int NSTH = FDIM / KC / KSPLIT;          // 48 stages per split
    int koff = blockIdx.z * NSTH;
    const float* Bw = g_w2t[uniq] + (size_t)e * FDIM * HDIM;
    const float* bb = (uniq ? b2u : b2c) + e * HDIM;
    const float* act = g_act[uniq];

    uint32_t A0a = smem_u32(sm);
    uint32_t B0a = smem_u32(sm + 3 * ABUF);

    int tid = threadIdx.x;
    int lr = tid >> 1, hh = tid & 1;
    const float* aptr = act + (size_t)(mt * BM + lr) * FDIM + hh * 16 + koff * KC;
    uint32_t adst = (uint32_t)(lr * 32 + ((hh ^ (lr & 1)) * 16)) * 4u;

    #define FFN2_ISSUE(s, bw) do {                                                 \
        uint32_t Aa = A0a + (uint32_t)(bw) * (ABUF * 4u);                          \
        uint32_t Ba = B0a + (uint32_t)(bw) * (BBUF * 4u);                          \
        const float* ap = aptr + (s) * KC;                                         \
        _Pragma("unroll")                                                          \
        for (int i = 0; i < 4; i++) CPA16(Aa + adst + i * 16u, ap + i * 4);        \
        _Pragma("unroll")                                                          \
        for (int i = 0; i < 4; i++) {                                              \
            int ft = i * 256 + tid;                                                \
            int c128 = ft >> 5, slot = ft & 31;                                    \
            int nb_l = c128 >> 1, kp_l = c128 & 1;                                 \
            const float* bp = Bw + ((size_t)(n0 / 8 + nb_l) * (FDIM / 16)          \
                                    + (2 * ((s) + koff) + kp_l)) * 128 + slot * 4; \
            CPA16(Ba + (uint32_t)(c128 * 128 + slot * 4) * 4u, bp);                \
        }                                                                          \
    } while (0)

    FFN2_ISSUE(0, 0); CPCOMMIT();
    FFN2_ISSUE(1, 1); CPCOMMIT();

    int wid = tid >> 5, lane = tid & 31;
    int wm = wid & 3, wn = wid >> 2;
    int r4 = lane >> 2, kl = lane & 3;
    int rpar4 = (r4 & 1) * 4;

    float acc[2][8][4];
    #pragma unroll
    for (int m = 0; m < 2; m++)
        #pragma unroll
        for (int j = 0; j < 8; j++)
            #pragma unroll
            for (int q = 0; q < 4; q++) acc[m][j][q] = 0.f;

    int bc = 0;
    for (int s = 0; s < NSTH; s++) {
        CPWAIT1();
        __syncthreads();
        int bw = bc + 2; if (bw >= 3) bw -= 3;
        if (s + 2 < NSTH) FFN2_ISSUE(s + 2, bw);
        CPCOMMIT();
        const float* As = sm + bc * ABUF;
        const float* Bs = sm + 3 * ABUF + bc * BBUF;
        #pragma unroll
        for (int kp = 0; kp < 2; kp++) {
            float4 va[2][2];
            int sc = ((kp * 4) ^ rpar4) + kl;
            #pragma unroll
            for (int m = 0; m < 2; m++) {
                int row0 = wm * 32 + m * 16 + r4;
                va[m][0] = *(const float4*)(As + row0 * 32 + sc * 4);
                va[m][1] = *(const float4*)(As + (row0 + 8) * 32 + sc * 4);
            }
            #pragma unroll
            for (int j = 0; j < 8; j++) {
                float4 b4 = *(const float4*)&Bs[(((wn * 8 + j) * 2 + kp) * 128) + lane * 4];
                #pragma unroll
                for (int m = 0; m < 2; m++) {
                    mma_tf32_16x8x8(acc[m][j], va[m][0].x, va[m][1].x,
                                    va[m][0].y, va[m][1].y, b4.x, b4.y);
                    mma_tf32_16x8x8(acc[m][j], va[m][0].z, va[m][1].z,
                                    va[m][0].w, va[m][1].w, b4.z, b4.w);
                }
            }
        }
        bc = (bc == 2) ? 0 : bc + 1;
    }
    #undef FFN2_ISSUE

    // epilogue: RED-accumulate partial (+bias only from split 0) into pre-zeroed out
    int addb = (koff == 0);
    #pragma unroll
    for (int m = 0; m < 2; m++) {
        int rbase = mt * BM + wm * 32 + m * 16 + r4;
        #pragma unroll
        for (int rr = 0; rr < 2; rr++) {
            int tok = idx[rbase + rr * 8];
            if (tok < 0) continue;
            float* orow = out + (size_t)tok * HDIM;
            #pragma unroll
            for (int j = 0; j < 8; j++) {
                int col = n0 + wn * 64 + j * 8 + 2 * kl;
                float bv0 = addb ? bb[col]     : 0.f;
                float bv1 = addb ? bb[col + 1] : 0.f;
                red_add(orow + col,     acc[m][j][rr * 2 + 0] + bv0);
                red_add(orow + col + 1, acc[m][j][rr * 2 + 1] + bv1);
            }
        }
    }
}

// ---------------- launch ----------------
extern "C" void kernel_launch(void* const* d_in, const int* in_sizes, int n_in,
                              void* d_out, int out_size) {
    const float* h   = (const float*)d_in[0];
    const float* Wsc = (const float*)d_in[1];
    const float* bsc = (const float*)d_in[2];
    const float* W1c = (const float*)d_in[3];
    const float* b1c = (const float*)d_in[4];
    const float* W2c = (const float*)d_in[5];
    const float* b2c = (const float*)d_in[6];
    const float* Wsu = (const float*)d_in[7];
    const float* bsu = (const float*)d_in[8];
    const float* W1u = (const float*)d_in[9];
    const float* b1u = (const float*)d_in[10];
    const float* W2u = (const float*)d_in[11];
    const float* b2u = (const float*)d_in[12];
    float* out = (float*)d_out;

    const int SMEM = 3 * (ABUF + BBUF) * 4;   // 98304 B
    cudaFuncSetAttribute(ffn1_mma, cudaFuncAttributeMaxDynamicSharedMemorySize, SMEM);
    cudaFuncSetAttribute(ffn2_mma, cudaFuncAttributeMaxDynamicSharedMemorySize, SMEM);

    // weight permutes + reset/zero (merged)
    permute_reset_kernel<<<PERM_BLOCKS + RESET_BLOCKS, 256>>>(W1c, W1u, W2c, W2u, out);

    // routing (router also produces rounded/permuted g_hr)
    router_kernel<<<512, 256>>>(h, Wsc, bsc, Wsu, bsu);
    drop_kernel<<<256, 256>>>();
    build_scatter_kernel<<<1, 256>>>();

    // FFN1 fused (common + unique)
    ffn1_mma<<<dim3(FDIM / BN, 2 * MAXT), 256, SMEM>>>(b1c, b1u);
    // FFN2 fused (common + unique) with split-K x2, RED epilogue into zeroed out
    ffn2_mma<<<dim3(HDIM / BN, 2 * MAXT, KSPLIT), 256, SMEM>>>(b2c, b2u, out);
}

// round 17
// speedup vs baseline: 1.0461x; 1.0048x over previous
#include <cuda_runtime.h>
#include <math.h>
#include <stdint.h>

// ---------------- problem constants ----------------
#define N_TOK 4096
#define HDIM  768
#define FDIM  3072
#define EC    4
#define EU    4
#define CAP   1024

#define BM    128
#define BN    128
#define KC    32              // K per stage (= 2 k-pair chunks of 16)
#define MAXT  36
#define NPOS  (MAXT * BM)
#define KSPLIT 2              // FFN2 split-K factor (R10-proven)

#define ABUF  4096            // floats per A stage buffer (128 rows x 32)
#define BBUF  4096            // floats per B stage buffer (32 x 128)

#define PERM_BLOCKS (16 * 576)   // weight-permute blocks
#define RESET_BLOCKS 592         // extra blocks doing reset/zero work

// ---------------- device scratch ----------------
__device__ float g_pmax_c[N_TOK];
__device__ int   g_route_c[N_TOK];
__device__ int   g_route_u[N_TOK];
__device__ int   g_dropped[N_TOK];
__device__ int   g_cnt_c[EC], g_cnt_u[EU];
__device__ int   g_cur_u[EU];
__device__ int   g_tileE_c[MAXT], g_tileE_u[MAXT];
__device__ int   g_nt_c, g_nt_u;
__device__ int   g_idx_c[NPOS], g_idx_u[NPOS];
__device__ float g_hr[(size_t)N_TOK * HDIM];                 // rna-rounded, frag-permuted
__device__ float g_act[2][(size_t)NPOS * FDIM];              // FFN1 out (frag-permuted)
__device__ float g_w1t[2][(size_t)EC * FDIM * HDIM];         // W1 pair-interleaved frag order
__device__ float g_w2t[2][(size_t)EC * FDIM * HDIM];         // W2 pair-interleaved frag order

// ---------------- helpers ----------------
__device__ __forceinline__ uint32_t smem_u32(const void* p) {
    uint32_t a;
    asm("{ .reg .u64 t; cvta.to.shared.u64 t, %1; cvt.u32.u64 %0, t; }" : "=r"(a) : "l"(p));
    return a;
}
__device__ __forceinline__ float rna_tf32(float v) {
    uint32_t u;
    asm("cvt.rna.tf32.f32 %0, %1;" : "=r"(u) : "f"(v));
    return __uint_as_float(u);
}
__device__ __forceinline__ float gelu_exact(float x) {
    return 0.5f * x * (1.0f + erff(x * 0.7071067811865476f));
}
__device__ __forceinline__ void red_add(float* p, float v) {
    asm volatile("red.global.add.f32 [%0], %1;" :: "l"(p), "f"(v) : "memory");
}
// position of column/k value c within its 16-group (A fragment layout)
__device__ __forceinline__ int kpos(int c) {
    return (c & ~15) + 4 * (c & 3) + ((c & 15) >> 2);
}
#define CPA16(dst, src)  asm volatile("cp.async.cg.shared.global [%0], [%1], 16;" :: "r"(dst), "l"(src))
#define CPCOMMIT()       asm volatile("cp.async.commit_group;" ::: "memory")
#define CPWAIT1()        asm volatile("cp.async.wait_group 1;" ::: "memory")

__device__ __forceinline__ void mma_tf32_16x8x8(float* c,
        float a0, float a1, float a2, float a3, float b0, float b1) {
    asm volatile(
        "mma.sync.aligned.m16n8k8.row.col.f32.tf32.tf32.f32 "
        "{%0,%1,%2,%3}, {%4,%5,%6,%7}, {%8,%9}, {%0,%1,%2,%3};"
        : "+f"(c[0]), "+f"(c[1]), "+f"(c[2]), "+f"(c[3])
        : "r"(__float_as_uint(a0)), "r"(__float_as_uint(a1)),
          "r"(__float_as_uint(a2)), "r"(__float_as_uint(a3)),
          "r"(__float_as_uint(b0)), "r"(__float_as_uint(b1)));
}

// ---------------- 1. permute weights (+ fold in reset/zero as extra blocks) ----------------
__global__ void __launch_bounds__(256) permute_reset_kernel(
        const float* __restrict__ W1c, const float* __restrict__ W1u,
        const float* __restrict__ W2c, const float* __restrict__ W2u,
        float* __restrict__ out) {
    __shared__ float t[32][136];
    int bid = blockIdx.x;
    int tid = threadIdx.x;
    if (bid >= PERM_BLOCKS) {
        // ---- reset/zero work ----
        int rb = bid - PERM_BLOCKS;
        int i = rb * 256 + tid;
        if (i < EC) g_cnt_c[i] = 0;
        if (i < EU) { g_cnt_u[i] = 0; g_cur_u[i] = 0; }
        int stride = RESET_BLOCKS * 256;
        for (int p = i; p < NPOS; p += stride) {
            g_idx_c[p] = -1;
            g_idx_u[p] = -1;
        }
        for (int p = i; p < N_TOK * HDIM / 4; p += stride)
            ((float4*)out)[p] = make_float4(0.f, 0.f, 0.f, 0.f);
        return;
    }
    const int TPW = 576;                            // tiles per (wg, expert)
    int which = bid / TPW;                          // 0..15
    int tile  = bid % TPW;
    int wg = which >> 2, e = which & 3;
    int Kd = (wg < 2) ? HDIM : FDIM;
    int Nd = (wg < 2) ? FDIM : HDIM;
    const float* srcs[4] = {W1c, W1u, W2c, W2u};
    float* dsts[4] = {g_w1t[0], g_w1t[1], g_w2t[0], g_w2t[1]};
    const float* s = srcs[wg] + (size_t)e * Kd * Nd;
    float* d = dsts[wg] + (size_t)e * Kd * Nd;
    int tilesN = Nd / 128;
    int k0 = (tile / tilesN) * 32, n0 = (tile % tilesN) * 128;

    int lr = tid >> 5, lc = (tid & 31) * 4;
    #pragma unroll
    for (int i = 0; i < 4; i++) {
        int r = lr + 8 * i;
        float4 v = *(const float4*)(s + (size_t)(k0 + r) * Nd + n0 + lc);
        *(float4*)&t[r][lc] = v;
    }
    __syncthreads();
    int lane = tid & 31;
    #pragma unroll
    for (int it = 0; it < 4; it++) {
        int chunk = (tid >> 5) + 8 * it;
        int kp = chunk & 1, nb = chunk >> 1;
        int kloc = kp * 16 + (lane & 3);
        int nloc = nb * 8 + (lane >> 2);
        float4 v;
        v.x = rna_tf32(t[kloc][nloc]);
        v.y = rna_tf32(t[kloc + 4][nloc]);
        v.z = rna_tf32(t[kloc + 8][nloc]);
        v.w = rna_tf32(t[kloc + 12][nloc]);
        size_t base = ((size_t)(n0 / 8 + nb) * (Kd / 16) + (k0 / 16 + kp)) * 128 + lane * 4;
        *(float4*)(d + base) = v;
    }
}

// ---------------- 2. router (+ fused rna/frag-permute of hidden states) ----------------
__global__ void router_kernel(const float* __restrict__ h,
                              const float* __restrict__ Wsc, const float* __restrict__ bsc,
                              const float* __restrict__ Wsu, const float* __restrict__ bsu) {
    int gw   = (blockIdx.x * blockDim.x + threadIdx.x) >> 5;
    int lane = threadIdx.x & 31;
    if (gw >= N_TOK) return;
    const float* hr = h + (size_t)gw * HDIM;
    float* hw = g_hr + (size_t)gw * HDIM;
    float a0=0,a1=0,a2=0,a3=0,u0=0,u1=0,u2=0,u3=0;
    for (int k = lane; k < HDIM; k += 32) {
        float x = hr[k];
        hw[kpos(k)] = rna_tf32(x);                      // fused round+permute
        float4 wc = *(const float4*)(Wsc + 4 * k);
        float4 wu = *(const float4*)(Wsu + 4 * k);
        a0 += x*wc.x; a1 += x*wc.y; a2 += x*wc.z; a3 += x*wc.w;
        u0 += x*wu.x; u1 += x*wu.y; u2 += x*wu.z; u3 += x*wu.w;
    }
    #pragma unroll
    for (int o = 16; o > 0; o >>= 1) {
        a0 += __shfl_down_sync(0xffffffffu, a0, o);
        a1 += __shfl_down_sync(0xffffffffu, a1, o);
        a2 += __shfl_down_sync(0xffffffffu, a2, o);
        a3 += __shfl_down_sync(0xffffffffu, a3, o);
        u0 += __shfl_down_sync(0xffffffffu, u0, o);
        u1 += __shfl_down_sync(0xffffffffu, u1, o);
        u2 += __shfl_down_sync(0xffffffffu, u2, o);
        u3 += __shfl_down_sync(0xffffffffu, u3, o);
    }
    if (lane == 0) {
        float lc[4] = {a0 + bsc[0], a1 + bsc[1], a2 + bsc[2], a3 + bsc[3]};
        float lu[4] = {u0 + bsu[0], u1 + bsu[1], u2 + bsu[2], u3 + bsu[3]};
        int rc = 0; float mc = lc[0];
        #pragma unroll
        for (int e = 1; e < EC; e++) if (lc[e] > mc) { mc = lc[e]; rc = e; }
        float s = 0.f;
        #pragma unroll
        for (int e = 0; e < EC; e++) s += expf(lc[e] - mc);
        g_pmax_c[gw]  = 1.0f / s;
        g_route_c[gw] = rc;
        atomicAdd(&g_cnt_c[rc], 1);
        int ru = 0; float mu = lu[0];
        #pragma unroll
        for (int e = 1; e < EU; e++) if (lu[e] > mu) { mu = lu[e]; ru = e; }
        g_route_u[gw] = ru;
    }
}

// ---------------- 3. capacity drop (lexsort rank) + atomic-free common scatter ----------------
// The lexsort rank is a bijection within each expert group -> write g_idx_c directly.
__global__ void __launch_bounds__(256) drop_kernel() {
    __shared__ float sp[N_TOK];
    __shared__ unsigned char sr[N_TOK];
    int tid = threadIdx.x;
    for (int j = tid; j < N_TOK; j += blockDim.x) {
        sp[j] = g_pmax_c[j];
        sr[j] = (unsigned char)g_route_c[j];
    }
    __syncthreads();
    int tloc = tid >> 4;                       // token within block (0..15)
    int sub  = tid & 15;                       // interleave phase (0..15)
    int i = blockIdx.x * 16 + tloc;            // global token
    float pi = sp[i];
    unsigned char re = sr[i];
    int cnt = 0;
    #pragma unroll 8
    for (int jj = 0; jj < N_TOK / 16; jj++) {
        int j = sub + 16 * jj;                 // interleaved: conflict-free LDS
        float pj = sp[j];
        bool before = (pj > pi) || (pj == pi && j < i);
        cnt += (sr[j] == re) && before;
    }
    #pragma unroll
    for (int o = 8; o > 0; o >>= 1)
        cnt += __shfl_down_sync(0xffffffffu, cnt, o, 16);
    if (sub == 0) {
        int drp = (cnt >= CAP) ? 1 : 0;
        g_dropped[i] = drp;
        if (drp) atomicAdd(&g_cnt_u[g_route_u[i]], 1);
        // common segment base for expert re (tile-padded prefix of g_cnt_c)
        int base = 0;
        #pragma unroll
        for (int e = 0; e < EC; e++)
            if (e < (int)re) base += ((g_cnt_c[e] + BM - 1) / BM) * BM;
        g_idx_c[base + cnt] = i;               // rank is unique within group
    }
}

// ---------------- 4. tile tables + unique scatter (parallel, 16 blocks) ----------------
__global__ void __launch_bounds__(256) scatter_u_kernel() {
    int tid = threadIdx.x;
    if (blockIdx.x == 0 && tid == 0) {
        int base = 0, t = 0;
        for (int e = 0; e < EC; e++) {
            int tiles = (g_cnt_c[e] + BM - 1) / BM;
            for (int i = 0; i < tiles; i++) g_tileE_c[t++] = e;
            base += tiles * BM;
        }
        g_nt_c = t;
        t = 0;
        for (int e = 0; e < EU; e++) {
            int tiles = (g_cnt_u[e] + BM - 1) / BM;
            for (int i = 0; i < tiles; i++) g_tileE_u[t++] = e;
        }
        g_nt_u = t;
    }
    int i = blockIdx.x * 256 + tid;
    if (i < N_TOK && g_dropped[i]) {
        int eu = g_route_u[i];
        int base = 0;
        #pragma unroll
        for (int e = 0; e < EU; e++)
            if (e < eu) base += ((g_cnt_u[e] + BM - 1) / BM) * BM;
        int q = base + atomicAdd(&g_cur_u[eu], 1);
        g_idx_u[q] = i;
    }
}

// ============================================================================
// GEMM core: triple-buffered, ONE barrier/stage, float4 A fragments (XOR swizzle)
// ============================================================================

// ---------------- 5. FFN1 (fused common+unique) ----------------
__global__ void __launch_bounds__(256) ffn1_mma(const float* __restrict__ b1c,
                                                const float* __restrict__ b1u) {
    extern __shared__ float sm[];
    int uniq = blockIdx.y >= MAXT;
    int mt = blockIdx.y - (uniq ? MAXT : 0);
    int nt = uniq ? g_nt_u : g_nt_c;
    if (mt >= nt) return;
    const int* idx = uniq ? g_idx_u : g_idx_c;
    int e  = (uniq ? g_tileE_u : g_tileE_c)[mt];
    int n0 = blockIdx.x * BN;
    const float* Bw = g_w1t[uniq] + (size_t)e * HDIM * FDIM;
    const float* bb = (uniq ? b1u : b1c) + e * FDIM;
    float* act = g_act[uniq];

    uint32_t A0a = smem_u32(sm);
    uint32_t B0a = smem_u32(sm + 3 * ABUF);

    int tid = threadIdx.x;
    int lr = tid >> 1, hh = tid & 1;
    int tokr = idx[mt * BM + lr];
    const float* aptr = g_hr + (size_t)(tokr < 0 ? 0 : tokr) * HDIM + hh * 16;
    uint32_t adst = (uint32_t)(lr * 32 + ((hh ^ (lr & 1)) * 16)) * 4u;

    const int NST = HDIM / KC;   // 24
    #define FFN1_ISSUE(s, bw) do {                                                 \
        uint32_t Aa = A0a + (uint32_t)(bw) * (ABUF * 4u);                          \
        uint32_t Ba = B0a + (uint32_t)(bw) * (BBUF * 4u);                          \
        const float* ap = aptr + (s) * KC;                                         \
        _Pragma("unroll")                                                          \
        for (int i = 0; i < 4; i++) CPA16(Aa + adst + i * 16u, ap + i * 4);        \
        _Pragma("unroll")                                                          \
        for (int i = 0; i < 4; i++) {                                              \
            int ft = i * 256 + tid;                                                \
            int c128 = ft >> 5, slot = ft & 31;                                    \
            int nb_l = c128 >> 1, kp_l = c128 & 1;                                 \
            const float* bp = Bw + ((size_t)(n0 / 8 + nb_l) * (HDIM / 16)          \
                                    + (2 * (s) + kp_l)) * 128 + slot * 4;          \
            CPA16(Ba + (uint32_t)(c128 * 128 + slot * 4) * 4u, bp);                \
        }                                                                          \
    } while (0)

    FFN1_ISSUE(0, 0); CPCOMMIT();
    FFN1_ISSUE(1, 1); CPCOMMIT();

    int wid = tid >> 5, lane = tid & 31;
    int wm = wid & 3, wn = wid >> 2;
    int r4 = lane >> 2, kl = lane & 3;
    int rpar4 = (r4 & 1) * 4;

    float acc[2][8][4];
    #pragma unroll
    for (int m = 0; m < 2; m++)
        #pragma unroll
        for (int j = 0; j < 8; j++)
            #pragma unroll
            for (int q = 0; q < 4; q++) acc[m][j][q] = 0.f;

    int bc = 0;
    for (int s = 0; s < NST; s++) {
        CPWAIT1();
        __syncthreads();
        int bw = bc + 2; if (bw >= 3) bw -= 3;
        if (s + 2 < NST) FFN1_ISSUE(s + 2, bw);
        CPCOMMIT();
        const float* As = sm + bc * ABUF;
        const float* Bs = sm + 3 * ABUF + bc * BBUF;
        #pragma unroll
        for (int kp = 0; kp < 2; kp++) {
            float4 va[2][2];
            int sc = ((kp * 4) ^ rpar4) + kl;
            #pragma unroll
            for (int m = 0; m < 2; m++) {
                int row0 = wm * 32 + m * 16 + r4;
                va[m][0] = *(const float4*)(As + row0 * 32 + sc * 4);
                va[m][1] = *(const float4*)(As + (row0 + 8) * 32 + sc * 4);
            }
            #pragma unroll
            for (int j = 0; j < 8; j++) {
                float4 b4 = *(const float4*)&Bs[(((wn * 8 + j) * 2 + kp) * 128) + lane * 4];
                #pragma unroll
                for (int m = 0; m < 2; m++) {
                    mma_tf32_16x8x8(acc[m][j], va[m][0].x, va[m][1].x,
                                    va[m][0].y, va[m][1].y, b4.x, b4.y);
                    mma_tf32_16x8x8(acc[m][j], va[m][0].z, va[m][1].z,
                                    va[m][0].w, va[m][1].w, b4.z, b4.w);
                }
            }
        }
        bc = (bc == 2) ? 0 : bc + 1;
    }
    #undef FFN1_ISSUE

    // epilogue: bias + gelu, scattered into frag-permuted positions of act
    #pragma unroll
    for (int m = 0; m < 2; m++) {
        int r0 = mt * BM + wm * 32 + m * 16 + r4;
        #pragma unroll
        for (int j = 0; j < 8; j++) {
            int gb = n0 + wn * 64 + j * 8;
            int c0 = gb + 2 * kl, c1 = c0 + 1;
            int p0 = kpos(c0), p1 = kpos(c1);
            float b0 = bb[c0], b1 = bb[c1];
            size_t ra = (size_t)r0 * FDIM;
            size_t rb = (size_t)(r0 + 8) * FDIM;
            act[ra + p0] = rna_tf32(gelu_exact(acc[m][j][0] + b0));
            act[ra + p1] = rna_tf32(gelu_exact(acc[m][j][1] + b1));
            act[rb + p0] = rna_tf32(gelu_exact(acc[m][j][2] + b0));
            act[rb + p1] = rna_tf32(gelu_exact(acc[m][j][3] + b1));
        }
    }
}

// ---------------- 6. FFN2 (fused common+unique, split-K x2): out += partial via RED ----------------
__global__ void __launch_bounds__(256) ffn2_mma(const float* __restrict__ b2c,
                                                const float* __restrict__ b2u,
                                                float* __restrict__ out) {
    extern __shared__ float sm[];
    int uniq = blockIdx.y >= MAXT;
    int mt = blockIdx.y - (uniq ? MAXT : 0);
    int nt = uniq ? g_nt_u : g_nt_c;
    if (mt >= nt) return;
    const int* idx = uniq ? g_idx_u : g_idx_c;
    int e  = (uniq ? g_tileE_u : g_tileE_c)[mt];
    int n0 = blockIdx.x * BN;
    const int NSTH = FDIM / KC / KSPLIT;          // 48 stages per split
    int koff = blockIdx.z * NSTH;
    const float* Bw = g_w2t[uniq] + (size_t)e * FDIM * HDIM;
    const float* bb = (uniq ? b2u : b2c) + e * HDIM;
    const float* act = g_act[uniq];

    uint32_t A0a = smem_u32(sm);
    uint32_t B0a = smem_u32(sm + 3 * ABUF);

    int tid = threadIdx.x;
    int lr = tid >> 1, hh = tid & 1;
    const float* aptr = act + (size_t)(mt * BM + lr) * FDIM + hh * 16 + koff * KC;
    uint32_t adst = (uint32_t)(lr * 32 + ((hh ^ (lr & 1)) * 16)) * 4u;

    #define FFN2_ISSUE(s, bw) do {                                                 \
        uint32_t Aa = A0a + (uint32_t)(bw) * (ABUF * 4u);                          \
        uint32_t Ba = B0a + (uint32_t)(bw) * (BBUF * 4u);                          \
        const float* ap = aptr + (s) * KC;                                         \
        _Pragma("unroll")                                                          \
        for (int i = 0; i < 4; i++) CPA16(Aa + adst + i * 16u, ap + i * 4);        \
        _Pragma("unroll")                                                          \
        for (int i = 0; i < 4; i++) {                                              \
            int ft = i * 256 + tid;                                                \
            int c128 = ft >> 5, slot = ft & 31;                                    \
            int nb_l = c128 >> 1, kp_l = c128 & 1;                                 \
            const float* bp = Bw + ((size_t)(n0 / 8 + nb_l) * (FDIM / 16)          \
                                    + (2 * ((s) + koff) + kp_l)) * 128 + slot * 4; \
            CPA16(Ba + (uint32_t)(c128 * 128 + slot * 4) * 4u, bp);                \
        }                                                                          \
    } while (0)

    FFN2_ISSUE(0, 0); CPCOMMIT();
    FFN2_ISSUE(1, 1); CPCOMMIT();

    int wid = tid >> 5, lane = tid & 31;
    int wm = wid & 3, wn = wid >> 2;
    int r4 = lane >> 2, kl = lane & 3;
    int rpar4 = (r4 & 1) * 4;

    float acc[2][8][4];
    #pragma unroll
    for (int m = 0; m < 2; m++)
        #pragma unroll
        for (int j = 0; j < 8; j++)
            #pragma unroll
            for (int q = 0; q < 4; q++) acc[m][j][q] = 0.f;

    int bc = 0;
    for (int s = 0; s < NSTH; s++) {
        CPWAIT1();
        __syncthreads();
        int bw = bc + 2; if (bw >= 3) bw -= 3;
        if (s + 2 < NSTH) FFN2_ISSUE(s + 2, bw);
        CPCOMMIT();
        const float* As = sm + bc * ABUF;
        const float* Bs = sm + 3 * ABUF + bc * BBUF;
        #pragma unroll
        for (int kp = 0; kp < 2; kp++) {
            float4 va[2][2];
            int sc = ((kp * 4) ^ rpar4) + kl;
            #pragma unroll
            for (int m = 0; m < 2; m++) {
                int row0 = wm * 32 + m * 16 + r4;
                va[m][0] = *(const float4*)(As + row0 * 32 + sc * 4);
                va[m][1] = *(const float4*)(As + (row0 + 8) * 32 + sc * 4);
            }
            #pragma unroll
            for (int j = 0; j < 8; j++) {
                float4 b4 = *(const float4*)&Bs[(((wn * 8 + j) * 2 + kp) * 128) + lane * 4];
                #pragma unroll
                for (int m = 0; m < 2; m++) {
                    mma_tf32_16x8x8(acc[m][j], va[m][0].x, va[m][1].x,
                                    va[m][0].y, va[m][1].y, b4.x, b4.y);
                    mma_tf32_16x8x8(acc[m][j], va[m][0].z, va[m][1].z,
                                    va[m][0].w, va[m][1].w, b4.z, b4.w);
                }
            }
        }
        bc = (bc == 2) ? 0 : bc + 1;
    }
    #undef FFN2_ISSUE

    // epilogue: RED-accumulate partial (+bias only from split 0) into pre-zeroed out
    int addb = (koff == 0);
    #pragma unroll
    for (int m = 0; m < 2; m++) {
        int rbase = mt * BM + wm * 32 + m * 16 + r4;
        #pragma unroll
        for (int rr = 0; rr < 2; rr++) {
            int tok = idx[rbase + rr * 8];
            if (tok < 0) continue;
            float* orow = out + (size_t)tok * HDIM;
            #pragma unroll
            for (int j = 0; j < 8; j++) {
                int col = n0 + wn * 64 + j * 8 + 2 * kl;
                float bv0 = addb ? bb[col]     : 0.f;
                float bv1 = addb ? bb[col + 1] : 0.f;
                red_add(orow + col,     acc[m][j][rr * 2 + 0] + bv0);
                red_add(orow + col + 1, acc[m][j][rr * 2 + 1] + bv1);
            }
        }
    }
}

// ---------------- launch ----------------
extern "C" void kernel_launch(void* const* d_in, const int* in_sizes, int n_in,
                              void* d_out, int out_size) {
    const float* h   = (const float*)d_in[0];
    const float* Wsc = (const float*)d_in[1];
    const float* bsc = (const float*)d_in[2];
    const float* W1c = (const float*)d_in[3];
    const float* b1c = (const float*)d_in[4];
    const float* W2c = (const float*)d_in[5];
    const float* b2c = (const float*)d_in[6];
    const float* Wsu = (const float*)d_in[7];
    const float* bsu = (const float*)d_in[8];
    const float* W1u = (const float*)d_in[9];
    const float* b1u = (const float*)d_in[10];
    const float* W2u = (const float*)d_in[11];
    const float* b2u = (const float*)d_in[12];
    float* out = (float*)d_out;

    const int SMEM = 3 * (ABUF + BBUF) * 4;   // 98304 B
    cudaFuncSetAttribute(ffn1_mma, cudaFuncAttributeMaxDynamicSharedMemorySize, SMEM);
    cudaFuncSetAttribute(ffn2_mma, cudaFuncAttributeMaxDynamicSharedMemorySize, SMEM);

    // weight permutes + reset/zero (merged)
    permute_reset_kernel<<<PERM_BLOCKS + RESET_BLOCKS, 256>>>(W1c, W1u, W2c, W2u, out);

    // routing (router also produces rounded/permuted g_hr)
    router_kernel<<<512, 256>>>(h, Wsc, bsc, Wsu, bsu);
    drop_kernel<<<256, 256>>>();            // also scatters common path (atomic-free)
    scatter_u_kernel<<<16, 256>>>();        // tile tables + unique scatter

    // FFN1 fused (common + unique)
    ffn1_mma<<<dim3(FDIM / BN, 2 * MAXT), 256, SMEM>>>(b1c, b1u);
    // FFN2 fused (common + unique) with split-K x2, RED epilogue into zeroed out
    ffn2_mma<<<dim3(HDIM / BN, 2 * MAXT, KSPLIT), 256, SMEM>>>(b2c, b2u, out);
}